// round 1
// baseline (speedup 1.0000x reference)
#include <cuda_runtime.h>
#include <cstdint>

#define NN   100000
#define NNZE 3200000
#define NIDX 50000

static inline int cdiv(int a, int b) { return (a + b - 1) / b; }

// ---------------- scratch (device globals; no allocations allowed) ----------
__device__ int   g_count[NN];
__device__ int   g_row_ptr[NN + 1];
__device__ int   g_cursor[NN];
__device__ int   g_csr_col[NNZE];
__device__ float g_csr_val[NNZE];
// Basis 1: [N][384] = [T0 | T1 | T2], F=128 each
__device__ float g_A1[(size_t)NN * 384];
// Basis 2: [N][768] = [H | T1h | T2h], F=256 each
__device__ float g_A2[(size_t)NN * 768];
// Permuted weights: W1p[(k*128+f)*256+j] = W1[(f*3+k)*256+j]
__device__ float g_W1p[384 * 256];
__device__ float g_W2p[768 * 64];

// ---------------- setup kernels ---------------------------------------------
__global__ void permute_W1(const float* __restrict__ W1) {
    int i = blockIdx.x * blockDim.x + threadIdx.x;
    if (i >= 384 * 256) return;
    int row = i / 256, j = i % 256;
    int k = row / 128, f = row % 128;
    g_W1p[i] = W1[(f * 3 + k) * 256 + j];
}

__global__ void permute_W2(const float* __restrict__ W2) {
    int i = blockIdx.x * blockDim.x + threadIdx.x;
    if (i >= 768 * 64) return;
    int row = i / 64, j = i % 64;
    int k = row / 256, f = row % 256;
    g_W2p[i] = W2[(f * 3 + k) * 64 + j];
}

__global__ void zero_counts() {
    int i = blockIdx.x * blockDim.x + threadIdx.x;
    if (i < NN) g_count[i] = 0;
}

__global__ void hist_kernel(const int* __restrict__ rows) {
    int i = blockIdx.x * blockDim.x + threadIdx.x;
    if (i < NNZE) atomicAdd(&g_count[rows[i]], 1);
}

// single-block scan over 100001 entries (warp-shuffle based, ~98 tiles)
__global__ void scan_kernel() {
    __shared__ int warp_sums[32];
    __shared__ int s_carry;
    int tid = threadIdx.x, lane = tid & 31, wid = tid >> 5;
    if (tid == 0) s_carry = 0;
    __syncthreads();
    for (int base = 0; base < NN; base += 1024) {
        int i = base + tid;
        int v = (i < NN) ? g_count[i] : 0;
        int x = v;
        #pragma unroll
        for (int off = 1; off < 32; off <<= 1) {
            int y = __shfl_up_sync(0xffffffffu, x, off);
            if (lane >= off) x += y;
        }
        if (lane == 31) warp_sums[wid] = x;
        __syncthreads();
        if (wid == 0) {
            int w = warp_sums[lane];
            #pragma unroll
            for (int off = 1; off < 32; off <<= 1) {
                int y = __shfl_up_sync(0xffffffffu, w, off);
                if (lane >= off) w += y;
            }
            warp_sums[lane] = w;
        }
        __syncthreads();
        int warp_off = (wid > 0) ? warp_sums[wid - 1] : 0;
        int incl = x + warp_off + s_carry;
        int excl = incl - v;
        if (i < NN) { g_row_ptr[i] = excl; g_cursor[i] = excl; }
        int tile_total = warp_sums[31];
        __syncthreads();
        if (tid == 0) s_carry += tile_total;
        __syncthreads();
    }
    if (threadIdx.x == 0) g_row_ptr[NN] = s_carry;
}

__global__ void scatter_kernel(const int* __restrict__ rows,
                               const int* __restrict__ cols,
                               const float* __restrict__ vals) {
    int i = blockIdx.x * blockDim.x + threadIdx.x;
    if (i >= NNZE) return;
    int r = rows[i];
    int pos = atomicAdd(&g_cursor[r], 1);
    g_csr_col[pos] = cols[i];
    g_csr_val[pos] = vals[i];
}

__global__ void copy_x(const float* __restrict__ x) {
    int i = blockIdx.x * blockDim.x + threadIdx.x;  // NN*32 float4
    if (i >= NN * 32) return;
    int n = i >> 5, f4 = i & 31;
    reinterpret_cast<float4*>(g_A1 + (size_t)n * 384)[f4] =
        reinterpret_cast<const float4*>(x)[i];
}

// ---------------- SpMM: one warp per row, register accumulation -------------
// dst[r] = alpha * sum_e val[e]*src[col[e]]  + beta * sub[r]
template <int NF4>
__global__ void spmm_kernel(const float* __restrict__ src,
                            float* __restrict__ dst,
                            const float* __restrict__ sub,
                            int stride, float alpha, float beta) {
    int gw = (blockIdx.x * blockDim.x + threadIdx.x) >> 5;
    if (gw >= NN) return;
    int lane = threadIdx.x & 31;
    int s = g_row_ptr[gw], e = g_row_ptr[gw + 1];

    float4 acc[NF4];
    #pragma unroll
    for (int q = 0; q < NF4; q++) acc[q] = make_float4(0.f, 0.f, 0.f, 0.f);

    int i = s;
    for (; i + 1 < e; i += 2) {
        int   c0 = g_csr_col[i],     c1 = g_csr_col[i + 1];
        float v0 = g_csr_val[i],     v1 = g_csr_val[i + 1];
        const float4* p0 = reinterpret_cast<const float4*>(src + (size_t)c0 * stride);
        const float4* p1 = reinterpret_cast<const float4*>(src + (size_t)c1 * stride);
        #pragma unroll
        for (int q = 0; q < NF4; q++) {
            float4 a = p0[lane + 32 * q];
            float4 b = p1[lane + 32 * q];
            acc[q].x += v0 * a.x + v1 * b.x;
            acc[q].y += v0 * a.y + v1 * b.y;
            acc[q].z += v0 * a.z + v1 * b.z;
            acc[q].w += v0 * a.w + v1 * b.w;
        }
    }
    if (i < e) {
        int c = g_csr_col[i];
        float v = g_csr_val[i];
        const float4* p = reinterpret_cast<const float4*>(src + (size_t)c * stride);
        #pragma unroll
        for (int q = 0; q < NF4; q++) {
            float4 a = p[lane + 32 * q];
            acc[q].x += v * a.x; acc[q].y += v * a.y;
            acc[q].z += v * a.z; acc[q].w += v * a.w;
        }
    }

    float4* d = reinterpret_cast<float4*>(dst + (size_t)gw * stride);
    if (beta != 0.0f) {
        const float4* sb = reinterpret_cast<const float4*>(sub + (size_t)gw * stride);
        #pragma unroll
        for (int q = 0; q < NF4; q++) {
            float4 sv = sb[lane + 32 * q];
            float4 o;
            o.x = alpha * acc[q].x + beta * sv.x;
            o.y = alpha * acc[q].y + beta * sv.y;
            o.z = alpha * acc[q].z + beta * sv.z;
            o.w = alpha * acc[q].w + beta * sv.w;
            d[lane + 32 * q] = o;
        }
    } else {
        #pragma unroll
        for (int q = 0; q < NF4; q++) {
            float4 o;
            o.x = alpha * acc[q].x; o.y = alpha * acc[q].y;
            o.z = alpha * acc[q].z; o.w = alpha * acc[q].w;
            d[lane + 32 * q] = o;
        }
    }
}

// ---------------- register-tiled SGEMM ---------------------------------------
// C[m, n0+.. ] = A[rowmap(m), :Ktot] @ B + bias ; optional ReLU, optional idx gather.
template <int BM, int BN, int BK, int TM, int TN, bool RELU, bool GATHER>
__global__ __launch_bounds__((BM / TM) * (BN / TN))
void gemm_kernel(const float* __restrict__ A, int lda,
                 const float* __restrict__ B, int ldb,
                 const float* __restrict__ bias,
                 float* __restrict__ C, int ldc,
                 int M, int Ktot,
                 const int* __restrict__ idx) {
    constexpr int THREADS = (BM / TM) * (BN / TN);
    __shared__ float As[BK][BM];
    __shared__ float Bs[BK][BN];
    __shared__ int rowmap[BM];

    int tid = threadIdx.x;
    int m0 = blockIdx.y * BM;
    int n0 = blockIdx.x * BN;

    for (int r = tid; r < BM; r += THREADS) {
        int m = m0 + r;
        rowmap[r] = (m < M) ? (GATHER ? idx[m] : m) : -1;
    }
    __syncthreads();

    constexpr int A_F4 = BM * BK / 4;
    constexpr int B_F4 = BK * BN / 4;
    int arow = tid / (BK / 4);
    int acol = (tid % (BK / 4)) * 4;
    int brow = tid / (BN / 4);
    int bcol = (tid % (BN / 4)) * 4;

    int tx = tid % (BN / TN);
    int ty = tid / (BN / TN);

    float acc[TM][TN];
    #pragma unroll
    for (int i = 0; i < TM; i++)
        #pragma unroll
        for (int j = 0; j < TN; j++) acc[i][j] = 0.f;

    for (int k0 = 0; k0 < Ktot; k0 += BK) {
        if (tid < A_F4) {
            int g = rowmap[arow];
            float4 av = make_float4(0.f, 0.f, 0.f, 0.f);
            if (g >= 0)
                av = *reinterpret_cast<const float4*>(A + (size_t)g * lda + k0 + acol);
            As[acol + 0][arow] = av.x;
            As[acol + 1][arow] = av.y;
            As[acol + 2][arow] = av.z;
            As[acol + 3][arow] = av.w;
        }
        if (tid < B_F4) {
            float4 bv = *reinterpret_cast<const float4*>(B + (size_t)(k0 + brow) * ldb + n0 + bcol);
            *reinterpret_cast<float4*>(&Bs[brow][bcol]) = bv;
        }
        __syncthreads();
        #pragma unroll
        for (int kk = 0; kk < BK; kk++) {
            float ra[TM], rb[TN];
            #pragma unroll
            for (int i = 0; i < TM; i += 4)
                *reinterpret_cast<float4*>(&ra[i]) =
                    *reinterpret_cast<const float4*>(&As[kk][ty * TM + i]);
            #pragma unroll
            for (int j = 0; j < TN; j += 4)
                *reinterpret_cast<float4*>(&rb[j]) =
                    *reinterpret_cast<const float4*>(&Bs[kk][tx * TN + j]);
            #pragma unroll
            for (int i = 0; i < TM; i++)
                #pragma unroll
                for (int j = 0; j < TN; j++)
                    acc[i][j] += ra[i] * rb[j];
        }
        __syncthreads();
    }

    #pragma unroll
    for (int i = 0; i < TM; i++) {
        int m = m0 + ty * TM + i;
        if (m >= M) continue;
        #pragma unroll
        for (int j = 0; j < TN; j += 4) {
            int n = n0 + tx * TN + j;
            float4 o;
            o.x = acc[i][j + 0] + bias[n + 0];
            o.y = acc[i][j + 1] + bias[n + 1];
            o.z = acc[i][j + 2] + bias[n + 2];
            o.w = acc[i][j + 3] + bias[n + 3];
            if (RELU) {
                o.x = fmaxf(o.x, 0.f); o.y = fmaxf(o.y, 0.f);
                o.z = fmaxf(o.z, 0.f); o.w = fmaxf(o.w, 0.f);
            }
            *reinterpret_cast<float4*>(C + (size_t)m * ldc + n) = o;
        }
    }
}

// ---------------- launch ------------------------------------------------------
extern "C" void kernel_launch(void* const* d_in, const int* in_sizes, int n_in,
                              void* d_out, int out_size) {
    const float* x    = (const float*)d_in[0];
    const float* vals = (const float*)d_in[1];
    const float* W1   = (const float*)d_in[2];
    const float* b1   = (const float*)d_in[3];
    const float* W2   = (const float*)d_in[4];
    const float* b2   = (const float*)d_in[5];
    const int*   rows = (const int*)d_in[6];
    const int*   cols = (const int*)d_in[7];
    const int*   idx  = (const int*)d_in[8];
    float*       out  = (float*)d_out;

    float *a1, *a2, *w1p, *w2p;
    cudaGetSymbolAddress((void**)&a1,  g_A1);
    cudaGetSymbolAddress((void**)&a2,  g_A2);
    cudaGetSymbolAddress((void**)&w1p, g_W1p);
    cudaGetSymbolAddress((void**)&w2p, g_W2p);

    // CSR build + weight permute
    permute_W1<<<cdiv(384 * 256, 256), 256>>>(W1);
    permute_W2<<<cdiv(768 * 64, 256), 256>>>(W2);
    zero_counts<<<cdiv(NN, 256), 256>>>();
    hist_kernel<<<cdiv(NNZE, 256), 256>>>(rows);
    scan_kernel<<<1, 1024>>>();
    scatter_kernel<<<cdiv(NNZE, 256), 256>>>(rows, cols, vals);

    // Basis 1 in g_A1 = [x | T1 | T2], stride 384
    copy_x<<<cdiv(NN * 32, 256), 256>>>(x);
    int spmm_blocks = cdiv(NN * 32, 256);
    // T1 = L x
    spmm_kernel<1><<<spmm_blocks, 256>>>(a1, a1 + 128, nullptr, 384, 1.0f, 0.0f);
    // T2 = 2 L T1 - x
    spmm_kernel<1><<<spmm_blocks, 256>>>(a1 + 128, a1 + 256, a1, 384, 2.0f, -1.0f);

    // H = relu(Basis1 @ W1p + b1) -> g_A2 cols [0,256), stride 768
    {
        dim3 grid(256 / 128, cdiv(NN, 128));
        gemm_kernel<128, 128, 8, 8, 8, true, false><<<grid, 256>>>(
            a1, 384, w1p, 256, b1, a2, 768, NN, 384, nullptr);
    }

    // Basis 2 in g_A2 = [H | T1h | T2h], stride 768
    spmm_kernel<2><<<spmm_blocks, 256>>>(a2, a2 + 256, nullptr, 768, 1.0f, 0.0f);
    spmm_kernel<2><<<spmm_blocks, 256>>>(a2 + 256, a2 + 512, a2, 768, 2.0f, -1.0f);

    // out[i] = Basis2[idx[i]] @ W2p + b2  (only the 50k gathered rows)
    {
        dim3 grid(1, cdiv(NIDX, 128));
        gemm_kernel<128, 64, 8, 8, 4, false, true><<<grid, 256>>>(
            a2, 768, w2p, 64, b2, out, 64, NIDX, 768, idx);
    }
}

// round 2
// speedup vs baseline: 1.1207x; 1.1207x over previous
#include <cuda_runtime.h>
#include <cstdint>

#define NN   100000
#define NNZE 3200000
#define NIDX 50000

static inline int cdiv(int a, int b) { return (a + b - 1) / b; }

// ---------------- scratch (device globals; no allocations allowed) ----------
__device__ int   g_count[NN];
__device__ int   g_row_ptr[NN + 1];
__device__ int   g_cursor[NN];
__device__ int   g_csr_col[NNZE];
__device__ float g_csr_val[NNZE];
// Basis 1: [N][384] = [T0 | T1 | T2], F=128 each
__device__ float g_A1[(size_t)NN * 384];
// H = relu(basis1 @ W1 + b1), compact [N][256]
__device__ float g_H[(size_t)NN * 256];
// Z = H @ [W2_1 | W2_2]  -> [N][128]  (U = cols 0:64, V = cols 64:128)
__device__ float g_Z[(size_t)NN * 128];
// S = L @ Z -> [N][128]  (LU = cols 0:64, LV = cols 64:128)
__device__ float g_S[(size_t)NN * 128];
// P = H @ (W2_0 - W2_2) + b2 -> [N][64]
__device__ float g_P[(size_t)NN * 64];
// Permuted weights
__device__ float g_W1p[384 * 256];   // W1p[(k*128+f)*256+j] = W1[(f*3+k)*256+j]
__device__ float g_W2cat[256 * 128]; // [f][0:64]=W2_1[f], [f][64:128]=W2_2[f]
__device__ float g_W2d[256 * 64];    // W2_0 - W2_2

// ---------------- setup kernels ---------------------------------------------
__global__ void permute_W1(const float* __restrict__ W1) {
    int i = blockIdx.x * blockDim.x + threadIdx.x;
    if (i >= 384 * 256) return;
    int row = i / 256, j = i % 256;
    int k = row / 128, f = row % 128;
    g_W1p[i] = W1[(f * 3 + k) * 256 + j];
}

__global__ void prep_W2(const float* __restrict__ W2) {
    int i = blockIdx.x * blockDim.x + threadIdx.x;
    if (i < 256 * 128) {
        int f = i / 128, j = i % 128;
        int k = (j < 64) ? 1 : 2;
        int jj = (j < 64) ? j : (j - 64);
        g_W2cat[i] = W2[(f * 3 + k) * 64 + jj];
    }
    if (i < 256 * 64) {
        int f = i / 64, j = i % 64;
        g_W2d[i] = W2[(f * 3 + 0) * 64 + j] - W2[(f * 3 + 2) * 64 + j];
    }
}

__global__ void zero_counts() {
    int i = blockIdx.x * blockDim.x + threadIdx.x;
    if (i < NN) g_count[i] = 0;
}

__global__ void hist_kernel(const int* __restrict__ rows) {
    int i = blockIdx.x * blockDim.x + threadIdx.x;
    if (i < NNZE) atomicAdd(&g_count[rows[i]], 1);
}

// single-block scan over 100001 entries (warp-shuffle based)
__global__ void scan_kernel() {
    __shared__ int warp_sums[32];
    __shared__ int s_carry;
    int tid = threadIdx.x, lane = tid & 31, wid = tid >> 5;
    if (tid == 0) s_carry = 0;
    __syncthreads();
    for (int base = 0; base < NN; base += 1024) {
        int i = base + tid;
        int v = (i < NN) ? g_count[i] : 0;
        int x = v;
        #pragma unroll
        for (int off = 1; off < 32; off <<= 1) {
            int y = __shfl_up_sync(0xffffffffu, x, off);
            if (lane >= off) x += y;
        }
        if (lane == 31) warp_sums[wid] = x;
        __syncthreads();
        if (wid == 0) {
            int w = warp_sums[lane];
            #pragma unroll
            for (int off = 1; off < 32; off <<= 1) {
                int y = __shfl_up_sync(0xffffffffu, w, off);
                if (lane >= off) w += y;
            }
            warp_sums[lane] = w;
        }
        __syncthreads();
        int warp_off = (wid > 0) ? warp_sums[wid - 1] : 0;
        int incl = x + warp_off + s_carry;
        int excl = incl - v;
        if (i < NN) { g_row_ptr[i] = excl; g_cursor[i] = excl; }
        int tile_total = warp_sums[31];
        __syncthreads();
        if (tid == 0) s_carry += tile_total;
        __syncthreads();
    }
    if (threadIdx.x == 0) g_row_ptr[NN] = s_carry;
}

__global__ void scatter_kernel(const int* __restrict__ rows,
                               const int* __restrict__ cols,
                               const float* __restrict__ vals) {
    int i = blockIdx.x * blockDim.x + threadIdx.x;
    if (i >= NNZE) return;
    int r = rows[i];
    int pos = atomicAdd(&g_cursor[r], 1);
    g_csr_col[pos] = cols[i];
    g_csr_val[pos] = vals[i];
}

__global__ void copy_x(const float* __restrict__ x) {
    int i = blockIdx.x * blockDim.x + threadIdx.x;  // NN*32 float4
    if (i >= NN * 32) return;
    int n = i >> 5, f4 = i & 31;
    reinterpret_cast<float4*>(g_A1 + (size_t)n * 384)[f4] =
        reinterpret_cast<const float4*>(x)[i];
}

// ---------------- SpMM: one warp per row, register accumulation -------------
// dst[r] = alpha * sum_e val[e]*src[col[e]]  + beta * sub[r]
template <int NF4>
__global__ void spmm_kernel(const float* __restrict__ src,
                            float* __restrict__ dst,
                            const float* __restrict__ sub,
                            int stride, float alpha, float beta) {
    int gw = (blockIdx.x * blockDim.x + threadIdx.x) >> 5;
    if (gw >= NN) return;
    int lane = threadIdx.x & 31;
    int s = g_row_ptr[gw], e = g_row_ptr[gw + 1];

    float4 acc[NF4];
    #pragma unroll
    for (int q = 0; q < NF4; q++) acc[q] = make_float4(0.f, 0.f, 0.f, 0.f);

    int i = s;
    for (; i + 1 < e; i += 2) {
        int   c0 = g_csr_col[i],     c1 = g_csr_col[i + 1];
        float v0 = g_csr_val[i],     v1 = g_csr_val[i + 1];
        const float4* p0 = reinterpret_cast<const float4*>(src + (size_t)c0 * stride);
        const float4* p1 = reinterpret_cast<const float4*>(src + (size_t)c1 * stride);
        #pragma unroll
        for (int q = 0; q < NF4; q++) {
            float4 a = p0[lane + 32 * q];
            float4 b = p1[lane + 32 * q];
            acc[q].x += v0 * a.x + v1 * b.x;
            acc[q].y += v0 * a.y + v1 * b.y;
            acc[q].z += v0 * a.z + v1 * b.z;
            acc[q].w += v0 * a.w + v1 * b.w;
        }
    }
    if (i < e) {
        int c = g_csr_col[i];
        float v = g_csr_val[i];
        const float4* p = reinterpret_cast<const float4*>(src + (size_t)c * stride);
        #pragma unroll
        for (int q = 0; q < NF4; q++) {
            float4 a = p[lane + 32 * q];
            acc[q].x += v * a.x; acc[q].y += v * a.y;
            acc[q].z += v * a.z; acc[q].w += v * a.w;
        }
    }

    float4* d = reinterpret_cast<float4*>(dst + (size_t)gw * stride);
    if (beta != 0.0f) {
        const float4* sb = reinterpret_cast<const float4*>(sub + (size_t)gw * stride);
        #pragma unroll
        for (int q = 0; q < NF4; q++) {
            float4 sv = sb[lane + 32 * q];
            float4 o;
            o.x = alpha * acc[q].x + beta * sv.x;
            o.y = alpha * acc[q].y + beta * sv.y;
            o.z = alpha * acc[q].z + beta * sv.z;
            o.w = alpha * acc[q].w + beta * sv.w;
            d[lane + 32 * q] = o;
        }
    } else {
        #pragma unroll
        for (int q = 0; q < NF4; q++) {
            float4 o;
            o.x = alpha * acc[q].x; o.y = alpha * acc[q].y;
            o.z = alpha * acc[q].z; o.w = alpha * acc[q].w;
            d[lane + 32 * q] = o;
        }
    }
}

// ---------------- final fused kernel -----------------------------------------
// out[i,:] = P[idx[i],:] + S[idx[i], 0:64] + 2 * sum_e val[e] * S[col[e], 64:128]
__global__ void final_kernel(const int* __restrict__ idx,
                             const float* __restrict__ S,
                             const float* __restrict__ P,
                             float* __restrict__ out) {
    int gw = (blockIdx.x * blockDim.x + threadIdx.x) >> 5;
    if (gw >= NIDX) return;
    int lane = threadIdx.x & 31;
    int r = idx[gw];
    int s = g_row_ptr[r], e = g_row_ptr[r + 1];

    float2 acc = make_float2(0.f, 0.f);
    int i = s;
    for (; i + 1 < e; i += 2) {
        int   c0 = g_csr_col[i],     c1 = g_csr_col[i + 1];
        float v0 = g_csr_val[i],     v1 = g_csr_val[i + 1];
        float2 a = reinterpret_cast<const float2*>(S + (size_t)c0 * 128 + 64)[lane];
        float2 b = reinterpret_cast<const float2*>(S + (size_t)c1 * 128 + 64)[lane];
        acc.x += v0 * a.x + v1 * b.x;
        acc.y += v0 * a.y + v1 * b.y;
    }
    if (i < e) {
        int c = g_csr_col[i];
        float v = g_csr_val[i];
        float2 a = reinterpret_cast<const float2*>(S + (size_t)c * 128 + 64)[lane];
        acc.x += v * a.x;
        acc.y += v * a.y;
    }

    float2 p  = reinterpret_cast<const float2*>(P + (size_t)r * 64)[lane];
    float2 lu = reinterpret_cast<const float2*>(S + (size_t)r * 128)[lane];
    float2 o;
    o.x = 2.0f * acc.x + p.x + lu.x;
    o.y = 2.0f * acc.y + p.y + lu.y;
    reinterpret_cast<float2*>(out + (size_t)gw * 64)[lane] = o;
}

// ---------------- register-tiled SGEMM ---------------------------------------
template <int BM, int BN, int BK, int TM, int TN, bool RELU, bool ADD_BIAS>
__global__ __launch_bounds__((BM / TM) * (BN / TN))
void gemm_kernel(const float* __restrict__ A, int lda,
                 const float* __restrict__ B, int ldb,
                 const float* __restrict__ bias,
                 float* __restrict__ C, int ldc,
                 int M, int Ktot) {
    constexpr int THREADS = (BM / TM) * (BN / TN);
    __shared__ float As[BK][BM];
    __shared__ float Bs[BK][BN];

    int tid = threadIdx.x;
    int m0 = blockIdx.y * BM;
    int n0 = blockIdx.x * BN;

    constexpr int A_F4 = BM * BK / 4;
    constexpr int B_F4 = BK * BN / 4;
    int arow = tid / (BK / 4);
    int acol = (tid % (BK / 4)) * 4;
    int brow = tid / (BN / 4);
    int bcol = (tid % (BN / 4)) * 4;

    int tx = tid % (BN / TN);
    int ty = tid / (BN / TN);

    float acc[TM][TN];
    #pragma unroll
    for (int i = 0; i < TM; i++)
        #pragma unroll
        for (int j = 0; j < TN; j++) acc[i][j] = 0.f;

    for (int k0 = 0; k0 < Ktot; k0 += BK) {
        if (tid < A_F4) {
            int m = m0 + arow;
            float4 av = make_float4(0.f, 0.f, 0.f, 0.f);
            if (m < M)
                av = *reinterpret_cast<const float4*>(A + (size_t)m * lda + k0 + acol);
            As[acol + 0][arow] = av.x;
            As[acol + 1][arow] = av.y;
            As[acol + 2][arow] = av.z;
            As[acol + 3][arow] = av.w;
        }
        if (tid < B_F4) {
            float4 bv = *reinterpret_cast<const float4*>(B + (size_t)(k0 + brow) * ldb + n0 + bcol);
            *reinterpret_cast<float4*>(&Bs[brow][bcol]) = bv;
        }
        __syncthreads();
        #pragma unroll
        for (int kk = 0; kk < BK; kk++) {
            float ra[TM], rb[TN];
            #pragma unroll
            for (int i = 0; i < TM; i += 4)
                *reinterpret_cast<float4*>(&ra[i]) =
                    *reinterpret_cast<const float4*>(&As[kk][ty * TM + i]);
            #pragma unroll
            for (int j = 0; j < TN; j += 4)
                *reinterpret_cast<float4*>(&rb[j]) =
                    *reinterpret_cast<const float4*>(&Bs[kk][tx * TN + j]);
            #pragma unroll
            for (int i = 0; i < TM; i++)
                #pragma unroll
                for (int j = 0; j < TN; j++)
                    acc[i][j] += ra[i] * rb[j];
        }
        __syncthreads();
    }

    #pragma unroll
    for (int i = 0; i < TM; i++) {
        int m = m0 + ty * TM + i;
        if (m >= M) continue;
        #pragma unroll
        for (int j = 0; j < TN; j += 4) {
            int n = n0 + tx * TN + j;
            float4 o;
            o.x = acc[i][j + 0]; o.y = acc[i][j + 1];
            o.z = acc[i][j + 2]; o.w = acc[i][j + 3];
            if (ADD_BIAS) {
                o.x += bias[n + 0]; o.y += bias[n + 1];
                o.z += bias[n + 2]; o.w += bias[n + 3];
            }
            if (RELU) {
                o.x = fmaxf(o.x, 0.f); o.y = fmaxf(o.y, 0.f);
                o.z = fmaxf(o.z, 0.f); o.w = fmaxf(o.w, 0.f);
            }
            *reinterpret_cast<float4*>(C + (size_t)m * ldc + n) = o;
        }
    }
}

// ---------------- launch ------------------------------------------------------
extern "C" void kernel_launch(void* const* d_in, const int* in_sizes, int n_in,
                              void* d_out, int out_size) {
    const float* x    = (const float*)d_in[0];
    const float* vals = (const float*)d_in[1];
    const float* W1   = (const float*)d_in[2];
    const float* b1   = (const float*)d_in[3];
    const float* W2   = (const float*)d_in[4];
    const float* b2   = (const float*)d_in[5];
    const int*   rows = (const int*)d_in[6];
    const int*   cols = (const int*)d_in[7];
    const int*   idx  = (const int*)d_in[8];
    float*       out  = (float*)d_out;

    float *a1, *h, *z, *s, *p, *w1p, *w2cat, *w2d;
    cudaGetSymbolAddress((void**)&a1,    g_A1);
    cudaGetSymbolAddress((void**)&h,     g_H);
    cudaGetSymbolAddress((void**)&z,     g_Z);
    cudaGetSymbolAddress((void**)&s,     g_S);
    cudaGetSymbolAddress((void**)&p,     g_P);
    cudaGetSymbolAddress((void**)&w1p,   g_W1p);
    cudaGetSymbolAddress((void**)&w2cat, g_W2cat);
    cudaGetSymbolAddress((void**)&w2d,   g_W2d);

    // CSR build + weight prep
    permute_W1<<<cdiv(384 * 256, 256), 256>>>(W1);
    prep_W2<<<cdiv(256 * 128, 256), 256>>>(W2);
    zero_counts<<<cdiv(NN, 256), 256>>>();
    hist_kernel<<<cdiv(NNZE, 256), 256>>>(rows);
    scan_kernel<<<1, 1024>>>();
    scatter_kernel<<<cdiv(NNZE, 256), 256>>>(rows, cols, vals);

    // Basis 1 in g_A1 = [x | T1 | T2], stride 384
    copy_x<<<cdiv(NN * 32, 256), 256>>>(x);
    int spmm_blocks = cdiv(NN * 32, 256);
    spmm_kernel<1><<<spmm_blocks, 256>>>(a1, a1 + 128, nullptr, 384, 1.0f, 0.0f);       // T1 = L x
    spmm_kernel<1><<<spmm_blocks, 256>>>(a1 + 128, a1 + 256, a1, 384, 2.0f, -1.0f);     // T2 = 2 L T1 - x

    // H = relu(Basis1 @ W1p + b1), compact stride 256
    {
        dim3 grid(256 / 128, cdiv(NN, 128));
        gemm_kernel<128, 128, 8, 8, 8, true, true><<<grid, 256>>>(
            a1, 384, w1p, 256, b1, h, 256, NN, 384);
    }

    // Z = H @ [W2_1 | W2_2]   (N x 128, no bias)
    {
        dim3 grid(1, cdiv(NN, 128));
        gemm_kernel<128, 128, 8, 8, 8, false, false><<<grid, 256>>>(
            h, 256, w2cat, 128, nullptr, z, 128, NN, 256);
    }
    // P = H @ (W2_0 - W2_2) + b2   (N x 64)
    {
        dim3 grid(1, cdiv(NN, 128));
        gemm_kernel<128, 64, 8, 8, 4, false, true><<<grid, 256>>>(
            h, 256, w2d, 64, b2, p, 64, NN, 256);
    }

    // S = L @ Z   (N x 128)
    spmm_kernel<1><<<spmm_blocks, 256>>>(z, s, nullptr, 128, 1.0f, 0.0f);

    // out[i] = P[idx[i]] + S[idx[i],0:64] + 2 * (L S[:,64:128])[idx[i]]
    final_kernel<<<cdiv(NIDX * 32, 256), 256>>>(idx, s, p, out);
}

// round 3
// speedup vs baseline: 1.6996x; 1.5165x over previous
#include <cuda_runtime.h>
#include <cstdint>

#define NN   100000
#define NNZE 3200000
#define NIDX 50000

static inline int cdiv(int a, int b) { return (a + b - 1) / b; }

// ---------------- scratch (device globals; no allocations allowed) ----------
__device__ int   g_count[NN];
__device__ int   g_row_ptr[NN + 1];
__device__ int   g_cursor[NN];
__device__ int   g_csr_col[NNZE];
__device__ float g_csr_val[NNZE];
// Basis 1: [N][384] = [T0 | T1 | T2], F=128 each
__device__ float g_A1[(size_t)NN * 384];
// H = relu(basis1 @ W1 + b1), compact [N][256]
__device__ float g_H[(size_t)NN * 256];
// Z = H @ [W2_1 | W2_2]  -> [N][128]
__device__ float g_Z[(size_t)NN * 128];
// S = L @ Z -> [N][128]
__device__ float g_S[(size_t)NN * 128];
// P = H @ (W2_0 - W2_2) + b2 -> [N][64]
__device__ float g_P[(size_t)NN * 64];
// Permuted weights
__device__ float g_W1p[384 * 256];
__device__ float g_W2cat[256 * 128];
__device__ float g_W2d[256 * 64];

// ---------------- setup kernels ---------------------------------------------
__global__ void permute_W1(const float* __restrict__ W1) {
    int i = blockIdx.x * blockDim.x + threadIdx.x;
    if (i >= 384 * 256) return;
    int row = i / 256, j = i % 256;
    int k = row / 128, f = row % 128;
    g_W1p[i] = W1[(f * 3 + k) * 256 + j];
}

__global__ void prep_W2(const float* __restrict__ W2) {
    int i = blockIdx.x * blockDim.x + threadIdx.x;
    if (i < 256 * 128) {
        int f = i / 128, j = i % 128;
        int k = (j < 64) ? 1 : 2;
        int jj = (j < 64) ? j : (j - 64);
        g_W2cat[i] = W2[(f * 3 + k) * 64 + jj];
    }
    if (i < 256 * 64) {
        int f = i / 64, j = i % 64;
        g_W2d[i] = W2[(f * 3 + 0) * 64 + j] - W2[(f * 3 + 2) * 64 + j];
    }
}

__global__ void zero_counts() {
    int i = blockIdx.x * blockDim.x + threadIdx.x;
    if (i < NN) g_count[i] = 0;
}

__global__ void hist_kernel(const int* __restrict__ rows) {
    int i = blockIdx.x * blockDim.x + threadIdx.x;
    if (i < NNZE) atomicAdd(&g_count[rows[i]], 1);
}

// single-block scan over 100001 entries
__global__ void scan_kernel() {
    __shared__ int warp_sums[32];
    __shared__ int s_carry;
    int tid = threadIdx.x, lane = tid & 31, wid = tid >> 5;
    if (tid == 0) s_carry = 0;
    __syncthreads();
    for (int base = 0; base < NN; base += 1024) {
        int i = base + tid;
        int v = (i < NN) ? g_count[i] : 0;
        int x = v;
        #pragma unroll
        for (int off = 1; off < 32; off <<= 1) {
            int y = __shfl_up_sync(0xffffffffu, x, off);
            if (lane >= off) x += y;
        }
        if (lane == 31) warp_sums[wid] = x;
        __syncthreads();
        if (wid == 0) {
            int w = warp_sums[lane];
            #pragma unroll
            for (int off = 1; off < 32; off <<= 1) {
                int y = __shfl_up_sync(0xffffffffu, w, off);
                if (lane >= off) w += y;
            }
            warp_sums[lane] = w;
        }
        __syncthreads();
        int warp_off = (wid > 0) ? warp_sums[wid - 1] : 0;
        int incl = x + warp_off + s_carry;
        int excl = incl - v;
        if (i < NN) { g_row_ptr[i] = excl; g_cursor[i] = excl; }
        int tile_total = warp_sums[31];
        __syncthreads();
        if (tid == 0) s_carry += tile_total;
        __syncthreads();
    }
    if (threadIdx.x == 0) g_row_ptr[NN] = s_carry;
}

__global__ void scatter_kernel(const int* __restrict__ rows,
                               const int* __restrict__ cols,
                               const float* __restrict__ vals) {
    int i = blockIdx.x * blockDim.x + threadIdx.x;
    if (i >= NNZE) return;
    int r = rows[i];
    int pos = atomicAdd(&g_cursor[r], 1);
    g_csr_col[pos] = cols[i];
    g_csr_val[pos] = vals[i];
}

__global__ void copy_x(const float* __restrict__ x) {
    int i = blockIdx.x * blockDim.x + threadIdx.x;  // NN*32 float4
    if (i >= NN * 32) return;
    int n = i >> 5, f4 = i & 31;
    reinterpret_cast<float4*>(g_A1 + (size_t)n * 384)[f4] =
        reinterpret_cast<const float4*>(x)[i];
}

// ---------------- SpMM: one warp per row, register accumulation -------------
template <int NF4>
__global__ void spmm_kernel(const float* __restrict__ src,
                            float* __restrict__ dst,
                            const float* __restrict__ sub,
                            int sstride, int dstride, float alpha, float beta) {
    int gw = (blockIdx.x * blockDim.x + threadIdx.x) >> 5;
    if (gw >= NN) return;
    int lane = threadIdx.x & 31;
    int s = g_row_ptr[gw], e = g_row_ptr[gw + 1];

    float4 acc[NF4];
    #pragma unroll
    for (int q = 0; q < NF4; q++) acc[q] = make_float4(0.f, 0.f, 0.f, 0.f);

    int i = s;
    for (; i + 1 < e; i += 2) {
        int   c0 = g_csr_col[i],     c1 = g_csr_col[i + 1];
        float v0 = g_csr_val[i],     v1 = g_csr_val[i + 1];
        const float4* p0 = reinterpret_cast<const float4*>(src + (size_t)c0 * sstride);
        const float4* p1 = reinterpret_cast<const float4*>(src + (size_t)c1 * sstride);
        #pragma unroll
        for (int q = 0; q < NF4; q++) {
            float4 a = p0[lane + 32 * q];
            float4 b = p1[lane + 32 * q];
            acc[q].x += v0 * a.x + v1 * b.x;
            acc[q].y += v0 * a.y + v1 * b.y;
            acc[q].z += v0 * a.z + v1 * b.z;
            acc[q].w += v0 * a.w + v1 * b.w;
        }
    }
    if (i < e) {
        int c = g_csr_col[i];
        float v = g_csr_val[i];
        const float4* p = reinterpret_cast<const float4*>(src + (size_t)c * sstride);
        #pragma unroll
        for (int q = 0; q < NF4; q++) {
            float4 a = p[lane + 32 * q];
            acc[q].x += v * a.x; acc[q].y += v * a.y;
            acc[q].z += v * a.z; acc[q].w += v * a.w;
        }
    }

    float4* d = reinterpret_cast<float4*>(dst + (size_t)gw * dstride);
    if (beta != 0.0f) {
        const float4* sb = reinterpret_cast<const float4*>(sub + (size_t)gw * dstride);
        #pragma unroll
        for (int q = 0; q < NF4; q++) {
            float4 sv = sb[lane + 32 * q];
            float4 o;
            o.x = alpha * acc[q].x + beta * sv.x;
            o.y = alpha * acc[q].y + beta * sv.y;
            o.z = alpha * acc[q].z + beta * sv.z;
            o.w = alpha * acc[q].w + beta * sv.w;
            d[lane + 32 * q] = o;
        }
    } else {
        #pragma unroll
        for (int q = 0; q < NF4; q++) {
            float4 o;
            o.x = alpha * acc[q].x; o.y = alpha * acc[q].y;
            o.z = alpha * acc[q].z; o.w = alpha * acc[q].w;
            d[lane + 32 * q] = o;
        }
    }
}

// ---------------- final fused kernel -----------------------------------------
// out[i,:] = P[idx[i],:] + S[idx[i], 0:64] + 2 * sum_e val[e] * S[col[e], 64:128]
__global__ void final_kernel(const int* __restrict__ idx,
                             const float* __restrict__ S,
                             const float* __restrict__ P,
                             float* __restrict__ out) {
    int gw = (blockIdx.x * blockDim.x + threadIdx.x) >> 5;
    if (gw >= NIDX) return;
    int lane = threadIdx.x & 31;
    int r = idx[gw];
    int s = g_row_ptr[r], e = g_row_ptr[r + 1];

    float2 acc = make_float2(0.f, 0.f);
    int i = s;
    for (; i + 1 < e; i += 2) {
        int   c0 = g_csr_col[i],     c1 = g_csr_col[i + 1];
        float v0 = g_csr_val[i],     v1 = g_csr_val[i + 1];
        float2 a = reinterpret_cast<const float2*>(S + (size_t)c0 * 128 + 64)[lane];
        float2 b = reinterpret_cast<const float2*>(S + (size_t)c1 * 128 + 64)[lane];
        acc.x += v0 * a.x + v1 * b.x;
        acc.y += v0 * a.y + v1 * b.y;
    }
    if (i < e) {
        int c = g_csr_col[i];
        float v = g_csr_val[i];
        float2 a = reinterpret_cast<const float2*>(S + (size_t)c * 128 + 64)[lane];
        acc.x += v * a.x;
        acc.y += v * a.y;
    }

    float2 p  = reinterpret_cast<const float2*>(P + (size_t)r * 64)[lane];
    float2 lu = reinterpret_cast<const float2*>(S + (size_t)r * 128)[lane];
    float2 o;
    o.x = 2.0f * acc.x + p.x + lu.x;
    o.y = 2.0f * acc.y + p.y + lu.y;
    reinterpret_cast<float2*>(out + (size_t)gw * 64)[lane] = o;
}

// ---------------- tf32 tensor-core GEMM ---------------------------------------
__device__ __forceinline__ float f2tf32(float x) {
    unsigned u;
    asm("cvt.rna.tf32.f32 %0, %1;" : "=r"(u) : "f"(x));
    return __uint_as_float(u);
}

template <int BM, int BN, int BK, int WM, int WN, bool RELU, bool ADD_BIAS>
__global__ __launch_bounds__((BM / WM) * (BN / WN) * 32)
void gemm_tf32_kernel(const float* __restrict__ A, int lda,
                      const float* __restrict__ B, int ldb,
                      const float* __restrict__ bias,
                      float* __restrict__ C, int ldc,
                      int M, int Ktot) {
    constexpr int WARPS_M = BM / WM;
    constexpr int WARPS_N = BN / WN;
    constexpr int THREADS = WARPS_M * WARPS_N * 32;
    constexpr int MT = WM / 16;
    constexpr int NT = WN / 8;
    constexpr int LDA_S = BM + 2;
    constexpr int LDB_S = BN + 8;

    __shared__ float As[BK][LDA_S];
    __shared__ float Bs[BK][LDB_S];

    int tid = threadIdx.x;
    int lane = tid & 31, wid = tid >> 5;
    int wm = (wid / WARPS_N) * WM;
    int wn = (wid % WARPS_N) * WN;
    int m0 = blockIdx.y * BM;
    int n0 = blockIdx.x * BN;

    float acc[MT][NT][4];
    #pragma unroll
    for (int mt = 0; mt < MT; mt++)
        #pragma unroll
        for (int nt = 0; nt < NT; nt++)
            #pragma unroll
            for (int q = 0; q < 4; q++) acc[mt][nt][q] = 0.f;

    constexpr int A_ITER = BM * BK / 4 / THREADS;
    constexpr int B_ITER = BK * BN / 4 / THREADS;

    for (int k0 = 0; k0 < Ktot; k0 += BK) {
        #pragma unroll
        for (int it = 0; it < A_ITER; it++) {
            int f4 = tid + it * THREADS;
            int ar = f4 / (BK / 4);
            int ac = (f4 % (BK / 4)) * 4;
            float4 v = make_float4(0.f, 0.f, 0.f, 0.f);
            int m = m0 + ar;
            if (m < M)
                v = *reinterpret_cast<const float4*>(A + (size_t)m * lda + k0 + ac);
            As[ac + 0][ar] = f2tf32(v.x);
            As[ac + 1][ar] = f2tf32(v.y);
            As[ac + 2][ar] = f2tf32(v.z);
            As[ac + 3][ar] = f2tf32(v.w);
        }
        #pragma unroll
        for (int it = 0; it < B_ITER; it++) {
            int f4 = tid + it * THREADS;
            int br = f4 / (BN / 4);
            int bc = (f4 % (BN / 4)) * 4;
            float4 v = *reinterpret_cast<const float4*>(B + (size_t)(k0 + br) * ldb + n0 + bc);
            Bs[br][bc + 0] = f2tf32(v.x);
            Bs[br][bc + 1] = f2tf32(v.y);
            Bs[br][bc + 2] = f2tf32(v.z);
            Bs[br][bc + 3] = f2tf32(v.w);
        }
        __syncthreads();
        #pragma unroll
        for (int kk = 0; kk < BK; kk += 8) {
            uint32_t af[MT][4], bf[NT][2];
            int kc = kk + (lane & 3);
            #pragma unroll
            for (int mt = 0; mt < MT; mt++) {
                int r = wm + mt * 16 + (lane >> 2);
                af[mt][0] = __float_as_uint(As[kc][r]);
                af[mt][1] = __float_as_uint(As[kc][r + 8]);
                af[mt][2] = __float_as_uint(As[kc + 4][r]);
                af[mt][3] = __float_as_uint(As[kc + 4][r + 8]);
            }
            #pragma unroll
            for (int nt = 0; nt < NT; nt++) {
                int n = wn + nt * 8 + (lane >> 2);
                bf[nt][0] = __float_as_uint(Bs[kc][n]);
                bf[nt][1] = __float_as_uint(Bs[kc + 4][n]);
            }
            #pragma unroll
            for (int mt = 0; mt < MT; mt++)
                #pragma unroll
                for (int nt = 0; nt < NT; nt++)
                    asm volatile(
                        "mma.sync.aligned.m16n8k8.row.col.f32.tf32.tf32.f32 "
                        "{%0,%1,%2,%3}, {%4,%5,%6,%7}, {%8,%9}, {%0,%1,%2,%3};"
                        : "+f"(acc[mt][nt][0]), "+f"(acc[mt][nt][1]),
                          "+f"(acc[mt][nt][2]), "+f"(acc[mt][nt][3])
                        : "r"(af[mt][0]), "r"(af[mt][1]), "r"(af[mt][2]), "r"(af[mt][3]),
                          "r"(bf[nt][0]), "r"(bf[nt][1]));
        }
        __syncthreads();
    }

    // Epilogue: c0/c1 at (row, col), c2/c3 at (row+8, col)
    #pragma unroll
    for (int mt = 0; mt < MT; mt++) {
        int r0 = m0 + wm + mt * 16 + (lane >> 2);
        #pragma unroll
        for (int nt = 0; nt < NT; nt++) {
            int n = n0 + wn + nt * 8 + (lane & 3) * 2;
            float bx = 0.f, by = 0.f;
            if (ADD_BIAS) { bx = bias[n]; by = bias[n + 1]; }
            float2 o0, o1;
            o0.x = acc[mt][nt][0] + bx; o0.y = acc[mt][nt][1] + by;
            o1.x = acc[mt][nt][2] + bx; o1.y = acc[mt][nt][3] + by;
            if (RELU) {
                o0.x = fmaxf(o0.x, 0.f); o0.y = fmaxf(o0.y, 0.f);
                o1.x = fmaxf(o1.x, 0.f); o1.y = fmaxf(o1.y, 0.f);
            }
            if (r0 < M)
                *reinterpret_cast<float2*>(C + (size_t)r0 * ldc + n) = o0;
            if (r0 + 8 < M)
                *reinterpret_cast<float2*>(C + (size_t)(r0 + 8) * ldc + n) = o1;
        }
    }
}

// ---------------- launch ------------------------------------------------------
extern "C" void kernel_launch(void* const* d_in, const int* in_sizes, int n_in,
                              void* d_out, int out_size) {
    const float* x    = (const float*)d_in[0];
    const float* vals = (const float*)d_in[1];
    const float* W1   = (const float*)d_in[2];
    const float* b1   = (const float*)d_in[3];
    const float* W2   = (const float*)d_in[4];
    const float* b2   = (const float*)d_in[5];
    const int*   rows = (const int*)d_in[6];
    const int*   cols = (const int*)d_in[7];
    const int*   idx  = (const int*)d_in[8];
    float*       out  = (float*)d_out;

    float *a1, *h, *z, *s, *p, *w1p, *w2cat, *w2d;
    cudaGetSymbolAddress((void**)&a1,    g_A1);
    cudaGetSymbolAddress((void**)&h,     g_H);
    cudaGetSymbolAddress((void**)&z,     g_Z);
    cudaGetSymbolAddress((void**)&s,     g_S);
    cudaGetSymbolAddress((void**)&p,     g_P);
    cudaGetSymbolAddress((void**)&w1p,   g_W1p);
    cudaGetSymbolAddress((void**)&w2cat, g_W2cat);
    cudaGetSymbolAddress((void**)&w2d,   g_W2d);

    // CSR build + weight prep
    permute_W1<<<cdiv(384 * 256, 256), 256>>>(W1);
    prep_W2<<<cdiv(256 * 128, 256), 256>>>(W2);
    zero_counts<<<cdiv(NN, 256), 256>>>();
    hist_kernel<<<cdiv(NNZE, 256), 256>>>(rows);
    scan_kernel<<<1, 1024>>>();
    scatter_kernel<<<cdiv(NNZE, 256), 256>>>(rows, cols, vals);

    // Basis 1 in g_A1 = [x | T1 | T2], stride 384
    copy_x<<<cdiv(NN * 32, 256), 256>>>(x);
    int spmm_blocks = cdiv(NN * 32, 256);
    spmm_kernel<1><<<spmm_blocks, 256>>>(a1, a1 + 128, nullptr, 384, 384, 1.0f, 0.0f);
    spmm_kernel<1><<<spmm_blocks, 256>>>(a1 + 128, a1 + 256, a1, 384, 384, 2.0f, -1.0f);

    // H = relu(Basis1 @ W1p + b1), stride 256  (tf32 tensor cores)
    {
        dim3 grid(256 / 128, cdiv(NN, 128));
        gemm_tf32_kernel<128, 128, 32, 32, 64, true, true><<<grid, 256>>>(
            a1, 384, w1p, 256, b1, h, 256, NN, 384);
    }

    // Z = H @ [W2_1 | W2_2]   (N x 128)
    {
        dim3 grid(1, cdiv(NN, 128));
        gemm_tf32_kernel<128, 128, 32, 32, 64, false, false><<<grid, 256>>>(
            h, 256, w2cat, 128, nullptr, z, 128, NN, 256);
    }
    // P = H @ (W2_0 - W2_2) + b2   (N x 64)
    {
        dim3 grid(1, cdiv(NN, 128));
        gemm_tf32_kernel<128, 64, 32, 32, 32, false, true><<<grid, 256>>>(
            h, 256, w2d, 64, b2, p, 64, NN, 256);
    }

    // S = L @ Z   (N x 128)
    spmm_kernel<1><<<spmm_blocks, 256>>>(z, s, nullptr, 128, 128, 1.0f, 0.0f);

    // out[i] = P[idx[i]] + S[idx[i],0:64] + 2 * (L S[:,64:128])[idx[i]]
    final_kernel<<<cdiv(NIDX * 32, 256), 256>>>(idx, s, p, out);
}

// round 4
// speedup vs baseline: 1.9727x; 1.1607x over previous
#include <cuda_runtime.h>
#include <cuda_fp16.h>
#include <cstdint>

#define NN   100000
#define NNZE 3200000
#define NIDX 50000

static inline int cdiv(int a, int b) { return (a + b - 1) / b; }

// ---------------- scratch (device globals) -----------------------------------
__device__ int    g_count[NN];
__device__ int    g_row_ptr[NN + 1];
__device__ int    g_cursor[NN];
__device__ int    g_mark[NN];
__device__ int    g_csr_col[NNZE];
__device__ float  g_csr_val[NNZE];
// Basis 1 fp32 for GEMM A: [N][384] = [T0 | T1 | T2]
__device__ float  g_A1[(size_t)NN * 384];
// fp16 gather sources
__device__ __half g_xh[(size_t)NN * 128];
__device__ __half g_T1h[(size_t)NN * 128];
__device__ __half g_Zh[(size_t)NN * 128];   // [0:64)=U, [64:128)=V
__device__ __half g_LVh[(size_t)NN * 64];
// H = relu(basis1 @ W1 + b1), fp32 [N][256]
__device__ float  g_H[(size_t)NN * 256];
// P = H @ (W2_0 - W2_2) + b2, fp32 [N][64]; final pass rewrites rows in place
__device__ float  g_P[(size_t)NN * 64];
// Permuted weights
__device__ float  g_W1p[384 * 256];
__device__ float  g_W2cat[256 * 128];
__device__ float  g_W2d[256 * 64];

// ---------------- setup kernels ---------------------------------------------
__global__ void permute_W1(const float* __restrict__ W1) {
    int i = blockIdx.x * blockDim.x + threadIdx.x;
    if (i >= 384 * 256) return;
    int row = i / 256, j = i % 256;
    int k = row / 128, f = row % 128;
    g_W1p[i] = W1[(f * 3 + k) * 256 + j];
}

__global__ void prep_W2(const float* __restrict__ W2) {
    int i = blockIdx.x * blockDim.x + threadIdx.x;
    if (i < 256 * 128) {
        int f = i / 128, j = i % 128;
        int k = (j < 64) ? 1 : 2;
        int jj = (j < 64) ? j : (j - 64);
        g_W2cat[i] = W2[(f * 3 + k) * 64 + jj];
    }
    if (i < 256 * 64) {
        int f = i / 64, j = i % 64;
        g_W2d[i] = W2[(f * 3 + 0) * 64 + j] - W2[(f * 3 + 2) * 64 + j];
    }
}

__global__ void zero_counts() {
    int i = blockIdx.x * blockDim.x + threadIdx.x;
    if (i < NN) { g_count[i] = 0; g_mark[i] = 0; }
}

__global__ void hist_kernel(const int* __restrict__ rows) {
    int i = blockIdx.x * blockDim.x + threadIdx.x;
    if (i < NNZE) atomicAdd(&g_count[rows[i]], 1);
}

__global__ void scan_kernel() {
    __shared__ int warp_sums[32];
    __shared__ int s_carry;
    int tid = threadIdx.x, lane = tid & 31, wid = tid >> 5;
    if (tid == 0) s_carry = 0;
    __syncthreads();
    for (int base = 0; base < NN; base += 1024) {
        int i = base + tid;
        int v = (i < NN) ? g_count[i] : 0;
        int x = v;
        #pragma unroll
        for (int off = 1; off < 32; off <<= 1) {
            int y = __shfl_up_sync(0xffffffffu, x, off);
            if (lane >= off) x += y;
        }
        if (lane == 31) warp_sums[wid] = x;
        __syncthreads();
        if (wid == 0) {
            int w = warp_sums[lane];
            #pragma unroll
            for (int off = 1; off < 32; off <<= 1) {
                int y = __shfl_up_sync(0xffffffffu, w, off);
                if (lane >= off) w += y;
            }
            warp_sums[lane] = w;
        }
        __syncthreads();
        int warp_off = (wid > 0) ? warp_sums[wid - 1] : 0;
        int incl = x + warp_off + s_carry;
        int excl = incl - v;
        if (i < NN) { g_row_ptr[i] = excl; g_cursor[i] = excl; }
        int tile_total = warp_sums[31];
        __syncthreads();
        if (tid == 0) s_carry += tile_total;
        __syncthreads();
    }
    if (threadIdx.x == 0) g_row_ptr[NN] = s_carry;
}

__global__ void scatter_kernel(const int* __restrict__ rows,
                               const int* __restrict__ cols,
                               const float* __restrict__ vals) {
    int i = blockIdx.x * blockDim.x + threadIdx.x;
    if (i >= NNZE) return;
    int r = rows[i];
    int pos = atomicAdd(&g_cursor[r], 1);
    g_csr_col[pos] = cols[i];
    g_csr_val[pos] = vals[i];
}

__global__ void mark_kernel(const int* __restrict__ idx) {
    int i = blockIdx.x * blockDim.x + threadIdx.x;
    if (i < NIDX) g_mark[idx[i]] = 1;
}

// x -> A1[:,0:128] fp32 and g_xh fp16
__global__ void copy_x(const float* __restrict__ x) {
    int i = blockIdx.x * blockDim.x + threadIdx.x;  // NN*32 float4
    if (i >= NN * 32) return;
    int n = i >> 5, f4 = i & 31;
    float4 v = reinterpret_cast<const float4*>(x)[i];
    reinterpret_cast<float4*>(g_A1 + (size_t)n * 384)[f4] = v;
    __half2 h0 = __floats2half2_rn(v.x, v.y);
    __half2 h1 = __floats2half2_rn(v.z, v.w);
    uint2 u;
    u.x = *reinterpret_cast<uint32_t*>(&h0);
    u.y = *reinterpret_cast<uint32_t*>(&h1);
    reinterpret_cast<uint2*>(g_xh + (size_t)n * 128)[f4] = u;
}

// ---------------- fp16-gather SpMM (128-wide), warp per row -------------------
// acc = sum val * srch[col] (4 floats/lane). Optionally:
//   dual: write acc fp32 to dst (stride 384) and fp16 to dsth
//   sub : write (2*acc - sub) fp32 to dst
__device__ __forceinline__ void gather_add_h128(const __half* __restrict__ srch,
                                                int c, float v, int lane, float4& acc) {
    uint2 u = reinterpret_cast<const uint2*>(srch + (size_t)c * 128)[lane];
    __half2 h0 = *reinterpret_cast<__half2*>(&u.x);
    __half2 h1 = *reinterpret_cast<__half2*>(&u.y);
    float2 f0 = __half22float2(h0);
    float2 f1 = __half22float2(h1);
    acc.x += v * f0.x; acc.y += v * f0.y;
    acc.z += v * f1.x; acc.w += v * f1.y;
}

template <bool DUAL, bool SUB>
__global__ void spmm128_kernel(const __half* __restrict__ srch,
                               float* __restrict__ dst,        // fp32, stride 384
                               __half* __restrict__ dsth,      // fp16, stride 128 (DUAL)
                               const float* __restrict__ sub)  // fp32, stride 384 (SUB)
{
    int gw = (blockIdx.x * blockDim.x + threadIdx.x) >> 5;
    if (gw >= NN) return;
    int lane = threadIdx.x & 31;
    int s = g_row_ptr[gw], e = g_row_ptr[gw + 1];

    float4 acc = make_float4(0.f, 0.f, 0.f, 0.f);
    int i = s;
    for (; i + 3 < e; i += 4) {
        int   c0 = g_csr_col[i],   c1 = g_csr_col[i+1];
        int   c2 = g_csr_col[i+2], c3 = g_csr_col[i+3];
        float v0 = g_csr_val[i],   v1 = g_csr_val[i+1];
        float v2 = g_csr_val[i+2], v3 = g_csr_val[i+3];
        gather_add_h128(srch, c0, v0, lane, acc);
        gather_add_h128(srch, c1, v1, lane, acc);
        gather_add_h128(srch, c2, v2, lane, acc);
        gather_add_h128(srch, c3, v3, lane, acc);
    }
    for (; i < e; i++)
        gather_add_h128(srch, g_csr_col[i], g_csr_val[i], lane, acc);

    if (SUB) {
        float4 sv = reinterpret_cast<const float4*>(sub + (size_t)gw * 384)[lane];
        acc.x = 2.f * acc.x - sv.x;
        acc.y = 2.f * acc.y - sv.y;
        acc.z = 2.f * acc.z - sv.z;
        acc.w = 2.f * acc.w - sv.w;
    }
    reinterpret_cast<float4*>(dst + (size_t)gw * 384)[lane] = acc;
    if (DUAL) {
        __half2 h0 = __floats2half2_rn(acc.x, acc.y);
        __half2 h1 = __floats2half2_rn(acc.z, acc.w);
        uint2 u;
        u.x = *reinterpret_cast<uint32_t*>(&h0);
        u.y = *reinterpret_cast<uint32_t*>(&h1);
        reinterpret_cast<uint2*>(dsth + (size_t)gw * 128)[lane] = u;
    }
}

// ---------------- LV = L @ V  (V = Zh cols 64:128), output fp16 64-wide -------
__global__ void spmm_lv_kernel() {
    int gw = (blockIdx.x * blockDim.x + threadIdx.x) >> 5;
    if (gw >= NN) return;
    int lane = threadIdx.x & 31;
    int s = g_row_ptr[gw], e = g_row_ptr[gw + 1];

    float2 acc = make_float2(0.f, 0.f);
    int i = s;
    for (; i + 3 < e; i += 4) {
        #pragma unroll
        for (int q = 0; q < 4; q++) {
            int c = g_csr_col[i + q];
            float v = g_csr_val[i + q];
            __half2 h = reinterpret_cast<const __half2*>(g_Zh + (size_t)c * 128 + 64)[lane];
            float2 f = __half22float2(h);
            acc.x += v * f.x; acc.y += v * f.y;
        }
    }
    for (; i < e; i++) {
        int c = g_csr_col[i];
        float v = g_csr_val[i];
        __half2 h = reinterpret_cast<const __half2*>(g_Zh + (size_t)c * 128 + 64)[lane];
        float2 f = __half22float2(h);
        acc.x += v * f.x; acc.y += v * f.y;
    }
    reinterpret_cast<__half2*>(g_LVh + (size_t)gw * 64)[lane] =
        __floats2half2_rn(acc.x, acc.y);
}

// ---------------- final: for marked rows, P[r] += LU[r] + 2*(L LV)[r] ---------
__global__ void final_rows_kernel() {
    int gw = (blockIdx.x * blockDim.x + threadIdx.x) >> 5;
    if (gw >= NN) return;
    if (g_mark[gw] == 0) return;
    int lane = threadIdx.x & 31;
    int s = g_row_ptr[gw], e = g_row_ptr[gw + 1];

    float2 aU = make_float2(0.f, 0.f);
    float2 aL = make_float2(0.f, 0.f);
    int i = s;
    for (; i + 1 < e; i += 2) {
        #pragma unroll
        for (int q = 0; q < 2; q++) {
            int c = g_csr_col[i + q];
            float v = g_csr_val[i + q];
            __half2 hu = reinterpret_cast<const __half2*>(g_Zh + (size_t)c * 128)[lane];
            __half2 hl = reinterpret_cast<const __half2*>(g_LVh + (size_t)c * 64)[lane];
            float2 fu = __half22float2(hu);
            float2 fl = __half22float2(hl);
            aU.x += v * fu.x; aU.y += v * fu.y;
            aL.x += v * fl.x; aL.y += v * fl.y;
        }
    }
    if (i < e) {
        int c = g_csr_col[i];
        float v = g_csr_val[i];
        __half2 hu = reinterpret_cast<const __half2*>(g_Zh + (size_t)c * 128)[lane];
        __half2 hl = reinterpret_cast<const __half2*>(g_LVh + (size_t)c * 64)[lane];
        float2 fu = __half22float2(hu);
        float2 fl = __half22float2(hl);
        aU.x += v * fu.x; aU.y += v * fu.y;
        aL.x += v * fl.x; aL.y += v * fl.y;
    }

    float2* pr = reinterpret_cast<float2*>(g_P + (size_t)gw * 64) + lane;
    float2 p = *pr;
    p.x += aU.x + 2.f * aL.x;
    p.y += aU.y + 2.f * aL.y;
    *pr = p;
}

__global__ void gather_out_kernel(const int* __restrict__ idx,
                                  float* __restrict__ out) {
    int i = blockIdx.x * blockDim.x + threadIdx.x;  // NIDX*16 float4
    if (i >= NIDX * 16) return;
    int n = i >> 4, f4 = i & 15;
    int r = idx[n];
    reinterpret_cast<float4*>(out + (size_t)n * 64)[f4] =
        reinterpret_cast<const float4*>(g_P + (size_t)r * 64)[f4];
}

// ---------------- tf32 tensor-core GEMM ---------------------------------------
__device__ __forceinline__ float f2tf32(float x) {
    unsigned u;
    asm("cvt.rna.tf32.f32 %0, %1;" : "=r"(u) : "f"(x));
    return __uint_as_float(u);
}

template <int BM, int BN, int BK, int WM, int WN, bool RELU, bool ADD_BIAS, bool HALF_OUT>
__global__ __launch_bounds__((BM / WM) * (BN / WN) * 32)
void gemm_tf32_kernel(const float* __restrict__ A, int lda,
                      const float* __restrict__ B, int ldb,
                      const float* __restrict__ bias,
                      void* __restrict__ Cv, int ldc,
                      int M, int Ktot) {
    constexpr int WARPS_M = BM / WM;
    constexpr int WARPS_N = BN / WN;
    constexpr int THREADS = WARPS_M * WARPS_N * 32;
    constexpr int MT = WM / 16;
    constexpr int NT = WN / 8;
    constexpr int LDA_S = BM + 2;
    constexpr int LDB_S = BN + 8;

    __shared__ float As[BK][LDA_S];
    __shared__ float Bs[BK][LDB_S];

    int tid = threadIdx.x;
    int lane = tid & 31, wid = tid >> 5;
    int wm = (wid / WARPS_N) * WM;
    int wn = (wid % WARPS_N) * WN;
    int m0 = blockIdx.y * BM;
    int n0 = blockIdx.x * BN;

    float acc[MT][NT][4];
    #pragma unroll
    for (int mt = 0; mt < MT; mt++)
        #pragma unroll
        for (int nt = 0; nt < NT; nt++)
            #pragma unroll
            for (int q = 0; q < 4; q++) acc[mt][nt][q] = 0.f;

    constexpr int A_ITER = BM * BK / 4 / THREADS;
    constexpr int B_ITER = BK * BN / 4 / THREADS;

    for (int k0 = 0; k0 < Ktot; k0 += BK) {
        #pragma unroll
        for (int it = 0; it < A_ITER; it++) {
            int f4 = tid + it * THREADS;
            int ar = f4 / (BK / 4);
            int ac = (f4 % (BK / 4)) * 4;
            float4 v = make_float4(0.f, 0.f, 0.f, 0.f);
            int m = m0 + ar;
            if (m < M)
                v = *reinterpret_cast<const float4*>(A + (size_t)m * lda + k0 + ac);
            As[ac + 0][ar] = f2tf32(v.x);
            As[ac + 1][ar] = f2tf32(v.y);
            As[ac + 2][ar] = f2tf32(v.z);
            As[ac + 3][ar] = f2tf32(v.w);
        }
        #pragma unroll
        for (int it = 0; it < B_ITER; it++) {
            int f4 = tid + it * THREADS;
            int br = f4 / (BN / 4);
            int bc = (f4 % (BN / 4)) * 4;
            float4 v = *reinterpret_cast<const float4*>(B + (size_t)(k0 + br) * ldb + n0 + bc);
            Bs[br][bc + 0] = f2tf32(v.x);
            Bs[br][bc + 1] = f2tf32(v.y);
            Bs[br][bc + 2] = f2tf32(v.z);
            Bs[br][bc + 3] = f2tf32(v.w);
        }
        __syncthreads();
        #pragma unroll
        for (int kk = 0; kk < BK; kk += 8) {
            uint32_t af[MT][4], bf[NT][2];
            int kc = kk + (lane & 3);
            #pragma unroll
            for (int mt = 0; mt < MT; mt++) {
                int r = wm + mt * 16 + (lane >> 2);
                af[mt][0] = __float_as_uint(As[kc][r]);
                af[mt][1] = __float_as_uint(As[kc][r + 8]);
                af[mt][2] = __float_as_uint(As[kc + 4][r]);
                af[mt][3] = __float_as_uint(As[kc + 4][r + 8]);
            }
            #pragma unroll
            for (int nt = 0; nt < NT; nt++) {
                int n = wn + nt * 8 + (lane >> 2);
                bf[nt][0] = __float_as_uint(Bs[kc][n]);
                bf[nt][1] = __float_as_uint(Bs[kc + 4][n]);
            }
            #pragma unroll
            for (int mt = 0; mt < MT; mt++)
                #pragma unroll
                for (int nt = 0; nt < NT; nt++)
                    asm volatile(
                        "mma.sync.aligned.m16n8k8.row.col.f32.tf32.tf32.f32 "
                        "{%0,%1,%2,%3}, {%4,%5,%6,%7}, {%8,%9}, {%0,%1,%2,%3};"
                        : "+f"(acc[mt][nt][0]), "+f"(acc[mt][nt][1]),
                          "+f"(acc[mt][nt][2]), "+f"(acc[mt][nt][3])
                        : "r"(af[mt][0]), "r"(af[mt][1]), "r"(af[mt][2]), "r"(af[mt][3]),
                          "r"(bf[nt][0]), "r"(bf[nt][1]));
        }
        __syncthreads();
    }

    #pragma unroll
    for (int mt = 0; mt < MT; mt++) {
        int r0 = m0 + wm + mt * 16 + (lane >> 2);
        #pragma unroll
        for (int nt = 0; nt < NT; nt++) {
            int n = n0 + wn + nt * 8 + (lane & 3) * 2;
            float bx = 0.f, by = 0.f;
            if (ADD_BIAS) { bx = bias[n]; by = bias[n + 1]; }
            float2 o0, o1;
            o0.x = acc[mt][nt][0] + bx; o0.y = acc[mt][nt][1] + by;
            o1.x = acc[mt][nt][2] + bx; o1.y = acc[mt][nt][3] + by;
            if (RELU) {
                o0.x = fmaxf(o0.x, 0.f); o0.y = fmaxf(o0.y, 0.f);
                o1.x = fmaxf(o1.x, 0.f); o1.y = fmaxf(o1.y, 0.f);
            }
            if (HALF_OUT) {
                __half* C = (__half*)Cv;
                if (r0 < M)
                    *reinterpret_cast<__half2*>(C + (size_t)r0 * ldc + n) =
                        __floats2half2_rn(o0.x, o0.y);
                if (r0 + 8 < M)
                    *reinterpret_cast<__half2*>(C + (size_t)(r0 + 8) * ldc + n) =
                        __floats2half2_rn(o1.x, o1.y);
            } else {
                float* C = (float*)Cv;
                if (r0 < M)
                    *reinterpret_cast<float2*>(C + (size_t)r0 * ldc + n) = o0;
                if (r0 + 8 < M)
                    *reinterpret_cast<float2*>(C + (size_t)(r0 + 8) * ldc + n) = o1;
            }
        }
    }
}

// ---------------- launch ------------------------------------------------------
extern "C" void kernel_launch(void* const* d_in, const int* in_sizes, int n_in,
                              void* d_out, int out_size) {
    const float* x    = (const float*)d_in[0];
    const float* vals = (const float*)d_in[1];
    const float* W1   = (const float*)d_in[2];
    const float* b1   = (const float*)d_in[3];
    const float* W2   = (const float*)d_in[4];
    const float* b2   = (const float*)d_in[5];
    const int*   rows = (const int*)d_in[6];
    const int*   cols = (const int*)d_in[7];
    const int*   idx  = (const int*)d_in[8];
    float*       out  = (float*)d_out;

    float *a1, *h, *p, *w1p, *w2cat, *w2d;
    __half *xh, *t1h, *zh;
    cudaGetSymbolAddress((void**)&a1,    g_A1);
    cudaGetSymbolAddress((void**)&h,     g_H);
    cudaGetSymbolAddress((void**)&p,     g_P);
    cudaGetSymbolAddress((void**)&w1p,   g_W1p);
    cudaGetSymbolAddress((void**)&w2cat, g_W2cat);
    cudaGetSymbolAddress((void**)&w2d,   g_W2d);
    cudaGetSymbolAddress((void**)&xh,    g_xh);
    cudaGetSymbolAddress((void**)&t1h,   g_T1h);
    cudaGetSymbolAddress((void**)&zh,    g_Zh);

    // CSR build + weight prep
    permute_W1<<<cdiv(384 * 256, 256), 256>>>(W1);
    prep_W2<<<cdiv(256 * 128, 256), 256>>>(W2);
    zero_counts<<<cdiv(NN, 256), 256>>>();
    hist_kernel<<<cdiv(NNZE, 256), 256>>>(rows);
    scan_kernel<<<1, 1024>>>();
    scatter_kernel<<<cdiv(NNZE, 256), 256>>>(rows, cols, vals);
    mark_kernel<<<cdiv(NIDX, 256), 256>>>(idx);

    // Layer-1 basis (fp16 gathers, fp32 accumulate)
    copy_x<<<cdiv(NN * 32, 256), 256>>>(x);
    int warp_blocks = cdiv(NN * 32, 256);
    // T1 = L x  -> A1[:,128:256] fp32 + T1h fp16
    spmm128_kernel<true, false><<<warp_blocks, 256>>>(xh, a1 + 128, t1h, nullptr);
    // T2 = 2 L T1 - x -> A1[:,256:384] fp32
    spmm128_kernel<false, true><<<warp_blocks, 256>>>(t1h, a1 + 256, nullptr, a1);

    // H = relu(Basis1 @ W1p + b1), fp32 stride 256
    {
        dim3 grid(256 / 128, cdiv(NN, 128));
        gemm_tf32_kernel<128, 128, 32, 32, 64, true, true, false><<<grid, 256>>>(
            a1, 384, w1p, 256, b1, h, 256, NN, 384);
    }
    // Z = H @ [W2_1 | W2_2] -> fp16 [N][128]
    {
        dim3 grid(1, cdiv(NN, 128));
        gemm_tf32_kernel<128, 128, 32, 32, 64, false, false, true><<<grid, 256>>>(
            h, 256, w2cat, 128, nullptr, zh, 128, NN, 256);
    }
    // P = H @ (W2_0 - W2_2) + b2 -> fp32 [N][64]
    {
        dim3 grid(1, cdiv(NN, 128));
        gemm_tf32_kernel<128, 64, 32, 32, 32, false, true, false><<<grid, 256>>>(
            h, 256, w2d, 64, b2, p, 64, NN, 256);
    }

    // LV = L @ V (fp16 out)
    spmm_lv_kernel<<<warp_blocks, 256>>>();
    // marked rows: P[r] += LU[r] + 2*(L LV)[r]
    final_rows_kernel<<<warp_blocks, 256>>>();
    // out[i] = P[idx[i]]
    gather_out_kernel<<<cdiv(NIDX * 16, 256), 256>>>(idx, out);
}